// round 13
// baseline (speedup 1.0000x reference)
#include <cuda_runtime.h>
#include <cstdint>
#include <math.h>

#define HH 256
#define WW 256
#define NPIX 65536
#define CCH 32

// ---------------- scratch ----------------
__device__ float g_D[2 * NPIX];              // reference-ordered patch SSD table
__device__ float g_N[20 * 4 * NPIX];         // normals: [(it*4+s)][bch][p]
__device__ float4 g_S[2 * NPIX];             // match state between kM_A and kM_B

struct AllKeys { uint32_t k[5][4][2]; };

// ---------------- threefry-2x32 ----------------
__host__ __device__ __forceinline__ uint32_t rotl32(uint32_t v, int d) {
#ifdef __CUDA_ARCH__
    return __funnelshift_l(v, v, d);
#else
    return (v << d) | (v >> (32 - d));
#endif
}

__host__ __device__ __forceinline__ void threefry(uint32_t k0, uint32_t k1,
                                                  uint32_t x0, uint32_t x1,
                                                  uint32_t& o0, uint32_t& o1) {
    uint32_t k2 = k0 ^ k1 ^ 0x1BD11BDAu;
    x0 += k0; x1 += k1;
    x0 += x1; x1 = rotl32(x1, 13); x1 ^= x0;
    x0 += x1; x1 = rotl32(x1, 15); x1 ^= x0;
    x0 += x1; x1 = rotl32(x1, 26); x1 ^= x0;
    x0 += x1; x1 = rotl32(x1, 6);  x1 ^= x0;
    x0 += k1; x1 += k2 + 1u;
    x0 += x1; x1 = rotl32(x1, 17); x1 ^= x0;
    x0 += x1; x1 = rotl32(x1, 29); x1 ^= x0;
    x0 += x1; x1 = rotl32(x1, 16); x1 ^= x0;
    x0 += x1; x1 = rotl32(x1, 24); x1 ^= x0;
    x0 += k2; x1 += k0 + 2u;
    x0 += x1; x1 = rotl32(x1, 13); x1 ^= x0;
    x0 += x1; x1 = rotl32(x1, 15); x1 ^= x0;
    x0 += x1; x1 = rotl32(x1, 26); x1 ^= x0;
    x0 += x1; x1 = rotl32(x1, 6);  x1 ^= x0;
    x0 += k0; x1 += k1 + 3u;
    x0 += x1; x1 = rotl32(x1, 17); x1 ^= x0;
    x0 += x1; x1 = rotl32(x1, 29); x1 ^= x0;
    x0 += x1; x1 = rotl32(x1, 16); x1 ^= x0;
    x0 += x1; x1 = rotl32(x1, 24); x1 ^= x0;
    x0 += k1; x1 += k2 + 4u;
    x0 += x1; x1 = rotl32(x1, 13); x1 ^= x0;
    x0 += x1; x1 = rotl32(x1, 15); x1 ^= x0;
    x0 += x1; x1 = rotl32(x1, 26); x1 ^= x0;
    x0 += x1; x1 = rotl32(x1, 6);  x1 ^= x0;
    x0 += k2; x1 += k0 + 5u;
    o0 = x0; o1 = x1;
}

__device__ __forceinline__ uint32_t rnd32(uint32_t k0, uint32_t k1, uint32_t i) {
    uint32_t o0, o1;
    threefry(k0, k1, 0u, i, o0, o1);
    return o0 ^ o1;
}

// ---------------- float helpers (XLA-matching: NO fma contraction) ----------------
__device__ __forceinline__ float bits_to_f01(uint32_t v) {
    return __fadd_rn(__uint_as_float((v >> 9) | 0x3F800000u), -1.0f);
}

__device__ __forceinline__ float erfinv_xla(float x) {
    float t = __fmul_rn(x, x);
    float w = -log1pf(-t);
    float p;
    if (w < 5.0f) {
        w = __fadd_rn(w, -2.5f);
        p = 2.81022636e-08f;
        p = __fadd_rn(3.43273939e-07f,  __fmul_rn(p, w));
        p = __fadd_rn(-3.5233877e-06f,  __fmul_rn(p, w));
        p = __fadd_rn(-4.39150654e-06f, __fmul_rn(p, w));
        p = __fadd_rn(0.00021858087f,   __fmul_rn(p, w));
        p = __fadd_rn(-0.00125372503f,  __fmul_rn(p, w));
        p = __fadd_rn(-0.00417768164f,  __fmul_rn(p, w));
        p = __fadd_rn(0.246640727f,     __fmul_rn(p, w));
        p = __fadd_rn(1.50140941f,      __fmul_rn(p, w));
    } else {
        w = __fadd_rn(__fsqrt_rn(w), -3.0f);
        p = -0.000200214257f;
        p = __fadd_rn(0.000100950558f,  __fmul_rn(p, w));
        p = __fadd_rn(0.00134934322f,   __fmul_rn(p, w));
        p = __fadd_rn(-0.00367342844f,  __fmul_rn(p, w));
        p = __fadd_rn(0.00573950773f,   __fmul_rn(p, w));
        p = __fadd_rn(-0.0076224613f,   __fmul_rn(p, w));
        p = __fadd_rn(0.00943887047f,   __fmul_rn(p, w));
        p = __fadd_rn(1.00167406f,      __fmul_rn(p, w));
        p = __fadd_rn(2.83297682f,      __fmul_rn(p, w));
    }
    return __fmul_rn(p, x);
}

__device__ __forceinline__ float normal_from_bits(uint32_t v) {
    float f = bits_to_f01(v);
    float u = __fadd_rn(__fmul_rn(f, 2.0f), -0.99999994f);
    u = fmaxf(-0.99999994f, u);
    return __fmul_rn(1.4142135623730951f, erfinv_xla(u));
}

__device__ __forceinline__ float clipc(float v) {
    return fminf(fmaxf(v, 0.0f), 255.0f);
}

__device__ __forceinline__ int daddr(int b, float y, float x) {
    int iy = __float2int_rn(y);
    int ix = __float2int_rn(x);
    iy = min(max(iy, 0), HH - 1);
    ix = min(max(ix, 0), WW - 1);
    return b * NPIX + iy * WW + ix;
}

// ---------------- kernel: fused SQ + strict-order D (smem halo tiles) ----------------
#define TSX 32
#define TSY 8
#define HX 34
#define HSLOTS (HX * 10)   // 340

__global__ __launch_bounds__(256, 4) void kSQD(const float* __restrict__ src,
                                               const float* __restrict__ tgt) {
    __shared__ float sq[CCH * HSLOTS];   // 43520 B
    int tid = threadIdx.x;
    int tb  = blockIdx.x;
    int tileX = tb & 7;
    int tileY = (tb >> 3) & 31;
    int b     = tb >> 8;
    int baseY = tileY * TSY - 1;
    int baseX = tileX * TSX - 1;

    {
        int j = tid;
        int yh = j / HX, xh = j % HX;
        int gy = baseY + yh, gx = baseX + xh;
        bool inb = ((unsigned)gy < HH) && ((unsigned)gx < WW);
        int gidx = (b * CCH) * NPIX + gy * WW + gx;
#pragma unroll
        for (int c = 0; c < CCH; c++) {
            float v = 0.0f;
            if (inb) {
                float d = __fsub_rn(__ldg(&src[gidx + c * NPIX]),
                                    __ldg(&tgt[gidx + c * NPIX]));
                v = __fmul_rn(d, d);
            }
            sq[c * HSLOTS + j] = v;
        }
        int j2 = tid + 256;
        if (j2 < HSLOTS) {
            int yh2 = j2 / HX, xh2 = j2 % HX;
            int gy2 = baseY + yh2, gx2 = baseX + xh2;
            bool inb2 = ((unsigned)gy2 < HH) && ((unsigned)gx2 < WW);
            int gidx2 = (b * CCH) * NPIX + gy2 * WW + gx2;
#pragma unroll
            for (int c = 0; c < CCH; c++) {
                float v = 0.0f;
                if (inb2) {
                    float d = __fsub_rn(__ldg(&src[gidx2 + c * NPIX]),
                                        __ldg(&tgt[gidx2 + c * NPIX]));
                    v = __fmul_rn(d, d);
                }
                sq[c * HSLOTS + j2] = v;
            }
        }
    }
    __syncthreads();

    int tx = tid & 31, ty = tid >> 5;
    float acc = 0.0f;
#pragma unroll
    for (int dy = 0; dy < 3; dy++) {
#pragma unroll
        for (int dx = 0; dx < 3; dx++) {
            const float* pb = &sq[(ty + dy) * HX + (tx + dx)];
#pragma unroll
            for (int c = 0; c < CCH; c++) {
                acc = __fadd_rn(acc, pb[c * HSLOTS]);
            }
        }
    }
    g_D[b * NPIX + (tileY * TSY + ty) * WW + (tileX * TSX + tx)] = acc;
}

// ---------------- kernel: normal table for iteration range [IT0, IT1) ----------------
// 512 persistent blocks: each thread owns gtid and gtid + 131072 (bit-identical
// evaluations; smaller grid leaves SM slots free for concurrent kernels).
template <int IT0, int IT1>
__global__ __launch_bounds__(256) void kRNG(AllKeys keys) {
    uint32_t t0 = (uint32_t)(blockIdx.x * 256 + threadIdx.x);   // 0..131071
#pragma unroll
    for (int it = IT0; it < IT1; it++) {
#pragma unroll
        for (int s = 0; s < 4; s++) {
            uint32_t base = (uint32_t)(it * 4 + s) * 262144u;
            uint32_t k0 = keys.k[it][s][0], k1 = keys.k[it][s][1];
            float n0 = normal_from_bits(rnd32(k0, k1, t0));
            float n1 = normal_from_bits(rnd32(k0, k1, t0 + 131072u));
            g_N[base + t0]           = n0;
            g_N[base + t0 + 131072u] = n1;
        }
    }
}

// ---------------- kernel: PatchMatch iterations [IT0, IT1) ----------------
template <int IT0, int IT1, bool INIT, bool FIN>
__global__ __launch_bounds__(256) void kM(float* __restrict__ out,
                                          uint32_t ka, uint32_t kb) {
    __shared__ float sy[2][256], sx[2][256], sd[2][256];
    int b   = blockIdx.x >> 8;
    int row = blockIdx.x & 255;
    int t   = threadIdx.x;
    int p   = (row << 8) | t;

    uint32_t ciy = (uint32_t)(b * 131072 + p);
    uint32_t cix = ciy + 65536u;

    float y, x, d;
    if (INIT) {
        y = __fmul_rn(bits_to_f01(rnd32(ka, kb, ciy)), 255.0f);
        x = __fmul_rn(bits_to_f01(rnd32(ka, kb, cix)), 255.0f);
        d = __ldg(&g_D[daddr(b, y, x)]);
    } else {
        float4 st = g_S[b * NPIX + p];
        y = st.x; x = st.y; d = st.z;
    }

    int tm = (t + 255) & 255;
    int tp = (t + 1) & 255;

#pragma unroll
    for (int it = IT0; it < IT1; it++) {
        int cb = (it - IT0) & 1;
        sy[cb][t] = y; sx[cb][t] = x; sd[cb][t] = d;

        float nrm[8];
#pragma unroll
        for (int s = 0; s < 4; s++) {
            uint32_t base = (uint32_t)(it * 4 + s) * 262144u;
            nrm[2 * s]     = __ldg(&g_N[base + ciy]);
            nrm[2 * s + 1] = __ldg(&g_N[base + cix]);
        }

        __syncthreads();
        float my = sy[cb][tm], mx = sx[cb][tm], md = sd[cb][tm];
        float qy = sy[cb][tp], qx = sx[cb][tp], qd = sd[cb][tp];

        // propagate(+1) at p and p+1, then propagate(-1) at p
        float c0y, c0x, c0d, c1y, c1x, c1d;
        if (md < d) { c0y = my; c0x = mx; c0d = md; } else { c0y = y; c0x = x; c0d = d; }
        if (d < qd) { c1y = y;  c1x = x;  c1d = d;  } else { c1y = qy; c1x = qx; c1d = qd; }
        if (c1d < c0d) { y = c1y; x = c1x; d = c1d; } else { y = c0y; x = c0x; d = c0d; }

        // ---- speculative pair (steps 0,1): scales 1.0, 0.5 ----
        {
            float a1y = clipc(__fadd_rn(y, __fmul_rn(nrm[0], 1.0f)));
            float a1x = clipc(__fadd_rn(x, __fmul_rn(nrm[1], 1.0f)));
            float r0y = clipc(__fadd_rn(y,   __fmul_rn(nrm[2], 0.5f)));
            float r0x = clipc(__fadd_rn(x,   __fmul_rn(nrm[3], 0.5f)));
            float r1y = clipc(__fadd_rn(a1y, __fmul_rn(nrm[2], 0.5f)));
            float r1x = clipc(__fadd_rn(a1x, __fmul_rn(nrm[3], 0.5f)));
            float d1  = __ldg(&g_D[daddr(b, a1y, a1x)]);
            float d20 = __ldg(&g_D[daddr(b, r0y, r0x)]);
            float d21 = __ldg(&g_D[daddr(b, r1y, r1x)]);
            bool acc1 = d1 < d;
            if (acc1) { y = a1y; x = a1x; d = d1; }
            float dv = acc1 ? d21 : d20;
            float cy = acc1 ? r1y : r0y;
            float cx = acc1 ? r1x : r0x;
            if (dv < d) { y = cy; x = cx; d = dv; }
        }
        // ---- speculative pair (steps 2,3): scales 0.25, 0.125 ----
        {
            float a1y = clipc(__fadd_rn(y, __fmul_rn(nrm[4], 0.25f)));
            float a1x = clipc(__fadd_rn(x, __fmul_rn(nrm[5], 0.25f)));
            float r0y = clipc(__fadd_rn(y,   __fmul_rn(nrm[6], 0.125f)));
            float r0x = clipc(__fadd_rn(x,   __fmul_rn(nrm[7], 0.125f)));
            float r1y = clipc(__fadd_rn(a1y, __fmul_rn(nrm[6], 0.125f)));
            float r1x = clipc(__fadd_rn(a1x, __fmul_rn(nrm[7], 0.125f)));
            float d1  = __ldg(&g_D[daddr(b, a1y, a1x)]);
            float d20 = __ldg(&g_D[daddr(b, r0y, r0x)]);
            float d21 = __ldg(&g_D[daddr(b, r1y, r1x)]);
            bool acc1 = d1 < d;
            if (acc1) { y = a1y; x = a1x; d = d1; }
            float dv = acc1 ? d21 : d20;
            float cy = acc1 ? r1y : r0y;
            float cx = acc1 ? r1x : r0x;
            if (dv < d) { y = cy; x = cx; d = dv; }
        }
    }

    if (FIN) {
        out[b * 131072 + p]        = y;
        out[b * 131072 + NPIX + p] = x;
    } else {
        g_S[b * NPIX + p] = make_float4(y, x, d, 0.0f);
    }
}

// ---------------- host: stream/event infra (created pre-baseline, host-side) ----------------
struct ForkCtx {
    cudaStream_t sA;
    cudaEvent_t eFork, eA, eB;
    ForkCtx() {
        int leastPrio = 0, greatestPrio = 0;
        cudaDeviceGetStreamPriorityRange(&leastPrio, &greatestPrio);
        cudaStreamCreateWithPriority(&sA, cudaStreamNonBlocking, leastPrio);
        cudaEventCreateWithFlags(&eFork, cudaEventDisableTiming);
        cudaEventCreateWithFlags(&eA, cudaEventDisableTiming);
        cudaEventCreateWithFlags(&eB, cudaEventDisableTiming);
    }
};
static ForkCtx g_fork;

extern "C" void kernel_launch(void* const* d_in, const int* in_sizes, int n_in,
                              void* d_out, int out_size) {
    const float* src = (const float*)d_in[0];
    const float* tgt = (const float*)d_in[1];
    float* out = (float*)d_out;
    (void)in_sizes; (void)n_in; (void)out_size;

    uint32_t ki0, ki1, kl0, kl1;
    threefry(0u, 1u, 0u, 0u, ki0, ki1);   // k_init
    threefry(0u, 1u, 0u, 1u, kl0, kl1);   // k_loop

    AllKeys keys;
    for (uint32_t t = 0; t < 5; t++) {
        uint32_t K0, K1;
        threefry(kl0, kl1, 0u, t, K0, K1);        // fold_in(k_loop, t)
        for (int s = 0; s < 4; s++) {
            uint32_t n0, n1, s0, s1;
            threefry(K0, K1, 0u, 0u, n0, n1);     // next key
            threefry(K0, K1, 0u, 1u, s0, s1);     // key for normal draw
            keys.k[t][s][0] = s0;
            keys.k[t][s][1] = s1;
            K0 = n0; K1 = n1;
        }
    }

    // fork low-priority RNG stream off the launch stream
    cudaEventRecord(g_fork.eFork, 0);
    cudaStreamWaitEvent(g_fork.sA, g_fork.eFork, 0);

    // stream A (low prio): RNG chain, 512 persistent blocks each
    kRNG<0, 3><<<512, 256, 0, g_fork.sA>>>(keys);
    cudaEventRecord(g_fork.eA, g_fork.sA);
    kRNG<3, 5><<<512, 256, 0, g_fork.sA>>>(keys);
    cudaEventRecord(g_fork.eB, g_fork.sA);

    // launch stream: D build (mem-bound, co-resident with kRNG<0,3>)
    kSQD<<<512, 256>>>(src, tgt);

    // match A: init + iterations 0..2 (needs D + N[0..2]); co-runs with kRNG<3,5>
    cudaStreamWaitEvent(0, g_fork.eA, 0);
    kM<0, 3, true, false><<<512, 256>>>(out, ki0, ki1);

    // match B: iterations 3..4 (needs N[3..4]); joins stream A
    cudaStreamWaitEvent(0, g_fork.eB, 0);
    kM<3, 5, false, true><<<512, 256>>>(out, ki0, ki1);
}

// round 14
// speedup vs baseline: 1.1762x; 1.1762x over previous
#include <cuda_runtime.h>
#include <cstdint>
#include <math.h>

#define HH 256
#define WW 256
#define NPIX 65536
#define CCH 32

// ---------------- scratch ----------------
__device__ float g_D[2 * NPIX];              // reference-ordered patch SSD table
__device__ float g_N[20 * 4 * NPIX];         // normals: [(it*4+s)][bch][p]

struct AllKeys { uint32_t k[5][4][2]; };

// ---------------- threefry-2x32 ----------------
__host__ __device__ __forceinline__ uint32_t rotl32(uint32_t v, int d) {
#ifdef __CUDA_ARCH__
    return __funnelshift_l(v, v, d);
#else
    return (v << d) | (v >> (32 - d));
#endif
}

__host__ __device__ __forceinline__ void threefry(uint32_t k0, uint32_t k1,
                                                  uint32_t x0, uint32_t x1,
                                                  uint32_t& o0, uint32_t& o1) {
    uint32_t k2 = k0 ^ k1 ^ 0x1BD11BDAu;
    x0 += k0; x1 += k1;
    x0 += x1; x1 = rotl32(x1, 13); x1 ^= x0;
    x0 += x1; x1 = rotl32(x1, 15); x1 ^= x0;
    x0 += x1; x1 = rotl32(x1, 26); x1 ^= x0;
    x0 += x1; x1 = rotl32(x1, 6);  x1 ^= x0;
    x0 += k1; x1 += k2 + 1u;
    x0 += x1; x1 = rotl32(x1, 17); x1 ^= x0;
    x0 += x1; x1 = rotl32(x1, 29); x1 ^= x0;
    x0 += x1; x1 = rotl32(x1, 16); x1 ^= x0;
    x0 += x1; x1 = rotl32(x1, 24); x1 ^= x0;
    x0 += k2; x1 += k0 + 2u;
    x0 += x1; x1 = rotl32(x1, 13); x1 ^= x0;
    x0 += x1; x1 = rotl32(x1, 15); x1 ^= x0;
    x0 += x1; x1 = rotl32(x1, 26); x1 ^= x0;
    x0 += x1; x1 = rotl32(x1, 6);  x1 ^= x0;
    x0 += k0; x1 += k1 + 3u;
    x0 += x1; x1 = rotl32(x1, 17); x1 ^= x0;
    x0 += x1; x1 = rotl32(x1, 29); x1 ^= x0;
    x0 += x1; x1 = rotl32(x1, 16); x1 ^= x0;
    x0 += x1; x1 = rotl32(x1, 24); x1 ^= x0;
    x0 += k1; x1 += k2 + 4u;
    x0 += x1; x1 = rotl32(x1, 13); x1 ^= x0;
    x0 += x1; x1 = rotl32(x1, 15); x1 ^= x0;
    x0 += x1; x1 = rotl32(x1, 26); x1 ^= x0;
    x0 += x1; x1 = rotl32(x1, 6);  x1 ^= x0;
    x0 += k2; x1 += k0 + 5u;
    o0 = x0; o1 = x1;
}

__device__ __forceinline__ uint32_t rnd32(uint32_t k0, uint32_t k1, uint32_t i) {
    uint32_t o0, o1;
    threefry(k0, k1, 0u, i, o0, o1);
    return o0 ^ o1;
}

// ---------------- float helpers (XLA-matching: NO fma contraction) ----------------
__device__ __forceinline__ float bits_to_f01(uint32_t v) {
    return __fadd_rn(__uint_as_float((v >> 9) | 0x3F800000u), -1.0f);
}

__device__ __forceinline__ float erfinv_xla(float x) {
    float t = __fmul_rn(x, x);
    float w = -log1pf(-t);
    float p;
    if (w < 5.0f) {
        w = __fadd_rn(w, -2.5f);
        p = 2.81022636e-08f;
        p = __fadd_rn(3.43273939e-07f,  __fmul_rn(p, w));
        p = __fadd_rn(-3.5233877e-06f,  __fmul_rn(p, w));
        p = __fadd_rn(-4.39150654e-06f, __fmul_rn(p, w));
        p = __fadd_rn(0.00021858087f,   __fmul_rn(p, w));
        p = __fadd_rn(-0.00125372503f,  __fmul_rn(p, w));
        p = __fadd_rn(-0.00417768164f,  __fmul_rn(p, w));
        p = __fadd_rn(0.246640727f,     __fmul_rn(p, w));
        p = __fadd_rn(1.50140941f,      __fmul_rn(p, w));
    } else {
        w = __fadd_rn(__fsqrt_rn(w), -3.0f);
        p = -0.000200214257f;
        p = __fadd_rn(0.000100950558f,  __fmul_rn(p, w));
        p = __fadd_rn(0.00134934322f,   __fmul_rn(p, w));
        p = __fadd_rn(-0.00367342844f,  __fmul_rn(p, w));
        p = __fadd_rn(0.00573950773f,   __fmul_rn(p, w));
        p = __fadd_rn(-0.0076224613f,   __fmul_rn(p, w));
        p = __fadd_rn(0.00943887047f,   __fmul_rn(p, w));
        p = __fadd_rn(1.00167406f,      __fmul_rn(p, w));
        p = __fadd_rn(2.83297682f,      __fmul_rn(p, w));
    }
    return __fmul_rn(p, x);
}

__device__ __forceinline__ float normal_from_bits(uint32_t v) {
    float f = bits_to_f01(v);
    float u = __fadd_rn(__fmul_rn(f, 2.0f), -0.99999994f);
    u = fmaxf(-0.99999994f, u);
    return __fmul_rn(1.4142135623730951f, erfinv_xla(u));
}

__device__ __forceinline__ float clipc(float v) {
    return fminf(fmaxf(v, 0.0f), 255.0f);
}

__device__ __forceinline__ int daddr(int b, float y, float x) {
    int iy = __float2int_rn(y);
    int ix = __float2int_rn(x);
    iy = min(max(iy, 0), HH - 1);
    ix = min(max(ix, 0), WW - 1);
    return b * NPIX + iy * WW + ix;
}

// ---------------- kernel 1: heterogeneous prep (RNG blocks FIRST) ----------------
// blocks [0, 1024):    normal table fill (20 threefry+erfinv per thread)
// blocks [1024, 1536): fused SQ + strict-order D via smem halo tiles
#define TSX 32
#define TSY 8
#define HX 34
#define HSLOTS (HX * 10)   // 340

__global__ __launch_bounds__(256, 4) void kPrep(const float* __restrict__ src,
                                                const float* __restrict__ tgt,
                                                AllKeys keys) {
    __shared__ float sq[CCH * HSLOTS];   // 43520 B
    int tid = threadIdx.x;
    int bi  = blockIdx.x;

    if (bi >= 1024) {
        // ---- SQ + D tile ----
        int tb = bi - 1024;
        int tileX = tb & 7;
        int tileY = (tb >> 3) & 31;
        int b     = tb >> 8;
        int baseY = tileY * TSY - 1;
        int baseX = tileX * TSX - 1;

        {
            int j = tid;
            int yh = j / HX, xh = j % HX;
            int gy = baseY + yh, gx = baseX + xh;
            bool inb = ((unsigned)gy < HH) && ((unsigned)gx < WW);
            int gidx = (b * CCH) * NPIX + gy * WW + gx;
#pragma unroll
            for (int c = 0; c < CCH; c++) {
                float v = 0.0f;
                if (inb) {
                    float d = __fsub_rn(__ldg(&src[gidx + c * NPIX]),
                                        __ldg(&tgt[gidx + c * NPIX]));
                    v = __fmul_rn(d, d);
                }
                sq[c * HSLOTS + j] = v;
            }
            int j2 = tid + 256;
            if (j2 < HSLOTS) {
                int yh2 = j2 / HX, xh2 = j2 % HX;
                int gy2 = baseY + yh2, gx2 = baseX + xh2;
                bool inb2 = ((unsigned)gy2 < HH) && ((unsigned)gx2 < WW);
                int gidx2 = (b * CCH) * NPIX + gy2 * WW + gx2;
#pragma unroll
                for (int c = 0; c < CCH; c++) {
                    float v = 0.0f;
                    if (inb2) {
                        float d = __fsub_rn(__ldg(&src[gidx2 + c * NPIX]),
                                            __ldg(&tgt[gidx2 + c * NPIX]));
                        v = __fmul_rn(d, d);
                    }
                    sq[c * HSLOTS + j2] = v;
                }
            }
        }
        __syncthreads();

        int tx = tid & 31, ty = tid >> 5;
        float acc = 0.0f;
#pragma unroll
        for (int dy = 0; dy < 3; dy++) {
#pragma unroll
            for (int dx = 0; dx < 3; dx++) {
                const float* pb = &sq[(ty + dy) * HX + (tx + dx)];
#pragma unroll
                for (int c = 0; c < CCH; c++) {
                    acc = __fadd_rn(acc, pb[c * HSLOTS]);
                }
            }
        }
        g_D[b * NPIX + (tileY * TSY + ty) * WW + (tileX * TSX + tx)] = acc;
    } else {
        // ---- normal table: thread <-> (bch, p), counter = gtid ----
        uint32_t gtid = (uint32_t)(bi * 256 + tid);   // 0..262143
#pragma unroll
        for (int it = 0; it < 5; it++) {
#pragma unroll
            for (int s = 0; s < 4; s++) {
                float n = normal_from_bits(
                    rnd32(keys.k[it][s][0], keys.k[it][s][1], gtid));
                g_N[(uint32_t)(it * 4 + s) * 262144u + gtid] = n;
            }
        }
    }
}

// ---------------- kernel 2: init + 5 iterations, halo-split rows ----------------
// One block owns a 64-pixel chunk of a row plus a 5-deep circular halo each
// side (window 74). After iteration k, window pixels [k, 74-k) are bit-correct;
// after 5 iterations exactly the 64 owned pixels [5, 69) survive. Redundant
// halo computation is bit-safe: each pixel update is a pure function of table
// lookups, identical in any block that computes it.
#define WIN 74
#define OWN 64
#define HALO 5

__global__ __launch_bounds__(96) void kMatch(float* __restrict__ out,
                                             uint32_t ka, uint32_t kb) {
    __shared__ float sy[2][WIN + 2], sx[2][WIN + 2], sd[2][WIN + 2];
    int bi  = blockIdx.x;                 // 0..2047
    int b   = bi >> 10;                   // batch
    int rem = bi & 1023;
    int row = rem >> 2;
    int seg = rem & 3;
    int base = seg * OWN;
    int wp  = threadIdx.x;                // 0..95; active if < WIN
    bool act = wp < WIN;

    int j = (base + wp - HALO) & 255;     // circular column
    int p = (row << 8) | j;

    uint32_t ciy = (uint32_t)(b * 131072 + p);
    uint32_t cix = ciy + 65536u;

    float y = 0.0f, x = 0.0f, d = 0.0f;
    if (act) {
        y = __fmul_rn(bits_to_f01(rnd32(ka, kb, ciy)), 255.0f);
        x = __fmul_rn(bits_to_f01(rnd32(ka, kb, cix)), 255.0f);
        d = __ldg(&g_D[daddr(b, y, x)]);
    }

    int tm = max(wp - 1, 0);              // clamped: edge values are eroded anyway
    int tp = min(wp + 1, WIN - 1);

#pragma unroll
    for (int it = 0; it < 5; it++) {
        int cb = it & 1;
        if (act) { sy[cb][wp] = y; sx[cb][wp] = x; sd[cb][wp] = d; }

        float nrm[8];
        if (act) {
#pragma unroll
            for (int s = 0; s < 4; s++) {
                uint32_t nb = (uint32_t)(it * 4 + s) * 262144u;
                nrm[2 * s]     = __ldg(&g_N[nb + ciy]);
                nrm[2 * s + 1] = __ldg(&g_N[nb + cix]);
            }
        }

        __syncthreads();
        float my = sy[cb][tm], mx = sx[cb][tm], md = sd[cb][tm];
        float qy = sy[cb][tp], qx = sx[cb][tp], qd = sd[cb][tp];
        // single sync per iteration: next iteration writes the other buffer

        if (act) {
            // propagate(+1) at j and j+1, then propagate(-1) at j
            float c0y, c0x, c0d, c1y, c1x, c1d;
            if (md < d) { c0y = my; c0x = mx; c0d = md; } else { c0y = y; c0x = x; c0d = d; }
            if (d < qd) { c1y = y;  c1x = x;  c1d = d;  } else { c1y = qy; c1x = qx; c1d = qd; }
            if (c1d < c0d) { y = c1y; x = c1x; d = c1d; } else { y = c0y; x = c0x; d = c0d; }

            // ---- speculative pair (steps 0,1): scales 1.0, 0.5 ----
            {
                float a1y = clipc(__fadd_rn(y, __fmul_rn(nrm[0], 1.0f)));
                float a1x = clipc(__fadd_rn(x, __fmul_rn(nrm[1], 1.0f)));
                float r0y = clipc(__fadd_rn(y,   __fmul_rn(nrm[2], 0.5f)));
                float r0x = clipc(__fadd_rn(x,   __fmul_rn(nrm[3], 0.5f)));
                float r1y = clipc(__fadd_rn(a1y, __fmul_rn(nrm[2], 0.5f)));
                float r1x = clipc(__fadd_rn(a1x, __fmul_rn(nrm[3], 0.5f)));
                float d1  = __ldg(&g_D[daddr(b, a1y, a1x)]);
                float d20 = __ldg(&g_D[daddr(b, r0y, r0x)]);
                float d21 = __ldg(&g_D[daddr(b, r1y, r1x)]);
                bool acc1 = d1 < d;
                if (acc1) { y = a1y; x = a1x; d = d1; }
                float dv = acc1 ? d21 : d20;
                float cy = acc1 ? r1y : r0y;
                float cx = acc1 ? r1x : r0x;
                if (dv < d) { y = cy; x = cx; d = dv; }
            }
            // ---- speculative pair (steps 2,3): scales 0.25, 0.125 ----
            {
                float a1y = clipc(__fadd_rn(y, __fmul_rn(nrm[4], 0.25f)));
                float a1x = clipc(__fadd_rn(x, __fmul_rn(nrm[5], 0.25f)));
                float r0y = clipc(__fadd_rn(y,   __fmul_rn(nrm[6], 0.125f)));
                float r0x = clipc(__fadd_rn(x,   __fmul_rn(nrm[7], 0.125f)));
                float r1y = clipc(__fadd_rn(a1y, __fmul_rn(nrm[6], 0.125f)));
                float r1x = clipc(__fadd_rn(a1x, __fmul_rn(nrm[7], 0.125f)));
                float d1  = __ldg(&g_D[daddr(b, a1y, a1x)]);
                float d20 = __ldg(&g_D[daddr(b, r0y, r0x)]);
                float d21 = __ldg(&g_D[daddr(b, r1y, r1x)]);
                bool acc1 = d1 < d;
                if (acc1) { y = a1y; x = a1x; d = d1; }
                float dv = acc1 ? d21 : d20;
                float cy = acc1 ? r1y : r0y;
                float cx = acc1 ? r1x : r0x;
                if (dv < d) { y = cy; x = cx; d = dv; }
            }
        }
    }

    if (wp >= HALO && wp < HALO + OWN) {
        out[b * 131072 + p]        = y;
        out[b * 131072 + NPIX + p] = x;
    }
}

// ---------------- host ----------------
extern "C" void kernel_launch(void* const* d_in, const int* in_sizes, int n_in,
                              void* d_out, int out_size) {
    const float* src = (const float*)d_in[0];
    const float* tgt = (const float*)d_in[1];
    float* out = (float*)d_out;
    (void)in_sizes; (void)n_in; (void)out_size;

    uint32_t ki0, ki1, kl0, kl1;
    threefry(0u, 1u, 0u, 0u, ki0, ki1);   // k_init
    threefry(0u, 1u, 0u, 1u, kl0, kl1);   // k_loop

    AllKeys keys;
    for (uint32_t t = 0; t < 5; t++) {
        uint32_t K0, K1;
        threefry(kl0, kl1, 0u, t, K0, K1);        // fold_in(k_loop, t)
        for (int s = 0; s < 4; s++) {
            uint32_t n0, n1, s0, s1;
            threefry(K0, K1, 0u, 0u, n0, n1);     // next key
            threefry(K0, K1, 0u, 1u, s0, s1);     // key for normal draw
            keys.k[t][s][0] = s0;
            keys.k[t][s][1] = s1;
            K0 = n0; K1 = n1;
        }
    }

    kPrep<<<1536, 256>>>(src, tgt, keys);
    kMatch<<<2048, 96>>>(out, ki0, ki1);
}

// round 15
// speedup vs baseline: 1.2282x; 1.0442x over previous
#include <cuda_runtime.h>
#include <cstdint>
#include <math.h>

#define HH 256
#define WW 256
#define NPIX 65536
#define CCH 32

// ---------------- scratch ----------------
__device__ float g_D[2 * NPIX];        // reference-ordered patch SSD table
__device__ float4 g_N4[5 * 4 * NPIX];  // normals: idx = it*262144 + gtid, (s0,s1,s2,s3)

struct AllKeys { uint32_t k[5][4][2]; };

// ---------------- threefry-2x32 ----------------
__host__ __device__ __forceinline__ uint32_t rotl32(uint32_t v, int d) {
#ifdef __CUDA_ARCH__
    return __funnelshift_l(v, v, d);
#else
    return (v << d) | (v >> (32 - d));
#endif
}

__host__ __device__ __forceinline__ void threefry(uint32_t k0, uint32_t k1,
                                                  uint32_t x0, uint32_t x1,
                                                  uint32_t& o0, uint32_t& o1) {
    uint32_t k2 = k0 ^ k1 ^ 0x1BD11BDAu;
    x0 += k0; x1 += k1;
    x0 += x1; x1 = rotl32(x1, 13); x1 ^= x0;
    x0 += x1; x1 = rotl32(x1, 15); x1 ^= x0;
    x0 += x1; x1 = rotl32(x1, 26); x1 ^= x0;
    x0 += x1; x1 = rotl32(x1, 6);  x1 ^= x0;
    x0 += k1; x1 += k2 + 1u;
    x0 += x1; x1 = rotl32(x1, 17); x1 ^= x0;
    x0 += x1; x1 = rotl32(x1, 29); x1 ^= x0;
    x0 += x1; x1 = rotl32(x1, 16); x1 ^= x0;
    x0 += x1; x1 = rotl32(x1, 24); x1 ^= x0;
    x0 += k2; x1 += k0 + 2u;
    x0 += x1; x1 = rotl32(x1, 13); x1 ^= x0;
    x0 += x1; x1 = rotl32(x1, 15); x1 ^= x0;
    x0 += x1; x1 = rotl32(x1, 26); x1 ^= x0;
    x0 += x1; x1 = rotl32(x1, 6);  x1 ^= x0;
    x0 += k0; x1 += k1 + 3u;
    x0 += x1; x1 = rotl32(x1, 17); x1 ^= x0;
    x0 += x1; x1 = rotl32(x1, 29); x1 ^= x0;
    x0 += x1; x1 = rotl32(x1, 16); x1 ^= x0;
    x0 += x1; x1 = rotl32(x1, 24); x1 ^= x0;
    x0 += k1; x1 += k2 + 4u;
    x0 += x1; x1 = rotl32(x1, 13); x1 ^= x0;
    x0 += x1; x1 = rotl32(x1, 15); x1 ^= x0;
    x0 += x1; x1 = rotl32(x1, 26); x1 ^= x0;
    x0 += x1; x1 = rotl32(x1, 6);  x1 ^= x0;
    x0 += k2; x1 += k0 + 5u;
    o0 = x0; o1 = x1;
}

__device__ __forceinline__ uint32_t rnd32(uint32_t k0, uint32_t k1, uint32_t i) {
    uint32_t o0, o1;
    threefry(k0, k1, 0u, i, o0, o1);
    return o0 ^ o1;
}

// ---------------- float helpers (XLA-matching: NO fma contraction) ----------------
__device__ __forceinline__ float bits_to_f01(uint32_t v) {
    return __fadd_rn(__uint_as_float((v >> 9) | 0x3F800000u), -1.0f);
}

__device__ __forceinline__ float erfinv_xla(float x) {
    float t = __fmul_rn(x, x);
    float w = -log1pf(-t);
    float p;
    if (w < 5.0f) {
        w = __fadd_rn(w, -2.5f);
        p = 2.81022636e-08f;
        p = __fadd_rn(3.43273939e-07f,  __fmul_rn(p, w));
        p = __fadd_rn(-3.5233877e-06f,  __fmul_rn(p, w));
        p = __fadd_rn(-4.39150654e-06f, __fmul_rn(p, w));
        p = __fadd_rn(0.00021858087f,   __fmul_rn(p, w));
        p = __fadd_rn(-0.00125372503f,  __fmul_rn(p, w));
        p = __fadd_rn(-0.00417768164f,  __fmul_rn(p, w));
        p = __fadd_rn(0.246640727f,     __fmul_rn(p, w));
        p = __fadd_rn(1.50140941f,      __fmul_rn(p, w));
    } else {
        w = __fadd_rn(__fsqrt_rn(w), -3.0f);
        p = -0.000200214257f;
        p = __fadd_rn(0.000100950558f,  __fmul_rn(p, w));
        p = __fadd_rn(0.00134934322f,   __fmul_rn(p, w));
        p = __fadd_rn(-0.00367342844f,  __fmul_rn(p, w));
        p = __fadd_rn(0.00573950773f,   __fmul_rn(p, w));
        p = __fadd_rn(-0.0076224613f,   __fmul_rn(p, w));
        p = __fadd_rn(0.00943887047f,   __fmul_rn(p, w));
        p = __fadd_rn(1.00167406f,      __fmul_rn(p, w));
        p = __fadd_rn(2.83297682f,      __fmul_rn(p, w));
    }
    return __fmul_rn(p, x);
}

__device__ __forceinline__ float normal_from_bits(uint32_t v) {
    float f = bits_to_f01(v);
    float u = __fadd_rn(__fmul_rn(f, 2.0f), -0.99999994f);
    u = fmaxf(-0.99999994f, u);
    return __fmul_rn(1.4142135623730951f, erfinv_xla(u));
}

__device__ __forceinline__ float clipc(float v) {
    return fminf(fmaxf(v, 0.0f), 255.0f);
}

__device__ __forceinline__ int daddr(int b, float y, float x) {
    int iy = __float2int_rn(y);
    int ix = __float2int_rn(x);
    iy = min(max(iy, 0), HH - 1);
    ix = min(max(ix, 0), WW - 1);
    return b * NPIX + iy * WW + ix;
}

// ---------------- kernel 1: heterogeneous prep (RNG blocks FIRST) ----------------
// blocks [0, 1024):    normal table fill (20 threefry+erfinv, 5 float4 stores)
// blocks [1024, 1536): fused SQ + strict-order D via smem halo tiles
#define TSX 32
#define TSY 8
#define HX 34
#define HSLOTS (HX * 10)   // 340

__global__ __launch_bounds__(256, 4) void kPrep(const float* __restrict__ src,
                                                const float* __restrict__ tgt,
                                                AllKeys keys) {
    __shared__ float sq[CCH * HSLOTS];   // 43520 B
    int tid = threadIdx.x;
    int bi  = blockIdx.x;

    if (bi >= 1024) {
        // ---- SQ + D tile ----
        int tb = bi - 1024;
        int tileX = tb & 7;
        int tileY = (tb >> 3) & 31;
        int b     = tb >> 8;
        int baseY = tileY * TSY - 1;
        int baseX = tileX * TSX - 1;

        {
            int j = tid;
            int yh = j / HX, xh = j % HX;
            int gy = baseY + yh, gx = baseX + xh;
            bool inb = ((unsigned)gy < HH) && ((unsigned)gx < WW);
            int gidx = (b * CCH) * NPIX + gy * WW + gx;
#pragma unroll
            for (int c = 0; c < CCH; c++) {
                float v = 0.0f;
                if (inb) {
                    float d = __fsub_rn(__ldg(&src[gidx + c * NPIX]),
                                        __ldg(&tgt[gidx + c * NPIX]));
                    v = __fmul_rn(d, d);
                }
                sq[c * HSLOTS + j] = v;
            }
            int j2 = tid + 256;
            if (j2 < HSLOTS) {
                int yh2 = j2 / HX, xh2 = j2 % HX;
                int gy2 = baseY + yh2, gx2 = baseX + xh2;
                bool inb2 = ((unsigned)gy2 < HH) && ((unsigned)gx2 < WW);
                int gidx2 = (b * CCH) * NPIX + gy2 * WW + gx2;
#pragma unroll
                for (int c = 0; c < CCH; c++) {
                    float v = 0.0f;
                    if (inb2) {
                        float d = __fsub_rn(__ldg(&src[gidx2 + c * NPIX]),
                                            __ldg(&tgt[gidx2 + c * NPIX]));
                        v = __fmul_rn(d, d);
                    }
                    sq[c * HSLOTS + j2] = v;
                }
            }
        }
        __syncthreads();

        int tx = tid & 31, ty = tid >> 5;
        float acc = 0.0f;
#pragma unroll
        for (int dy = 0; dy < 3; dy++) {
#pragma unroll
            for (int dx = 0; dx < 3; dx++) {
                const float* pb = &sq[(ty + dy) * HX + (tx + dx)];
#pragma unroll
                for (int c = 0; c < CCH; c++) {
                    acc = __fadd_rn(acc, pb[c * HSLOTS]);
                }
            }
        }
        g_D[b * NPIX + (tileY * TSY + ty) * WW + (tileX * TSX + tx)] = acc;
    } else {
        // ---- normal table: thread <-> counter gtid; float4 (s0..s3) per iter ----
        uint32_t gtid = (uint32_t)(bi * 256 + tid);   // 0..262143
#pragma unroll
        for (int it = 0; it < 5; it++) {
            float n0 = normal_from_bits(rnd32(keys.k[it][0][0], keys.k[it][0][1], gtid));
            float n1 = normal_from_bits(rnd32(keys.k[it][1][0], keys.k[it][1][1], gtid));
            float n2 = normal_from_bits(rnd32(keys.k[it][2][0], keys.k[it][2][1], gtid));
            float n3 = normal_from_bits(rnd32(keys.k[it][3][0], keys.k[it][3][1], gtid));
            g_N4[(uint32_t)it * 262144u + gtid] = make_float4(n0, n1, n2, n3);
        }
    }
}

// ---------------- kernel 2: init + 5 iterations, halo-split rows ----------------
// One block owns 128 pixels of a row + 5-deep circular halo each side (window
// 138). After iteration k, window pixels [k, 138-k) are bit-correct; after 5
// iterations the 128 owned pixels [5, 133) survive. Redundant halo math is
// bit-safe (pure function of table lookups).
#define WIN 138
#define OWN 128
#define HALO 5
#define MTHREADS 160

__global__ __launch_bounds__(MTHREADS) void kMatch(float* __restrict__ out,
                                                   uint32_t ka, uint32_t kb) {
    __shared__ float sy[2][WIN + 2], sx[2][WIN + 2], sd[2][WIN + 2];
    int bi  = blockIdx.x;                 // 0..1023
    int b   = bi >> 9;                    // batch
    int rem = bi & 511;
    int row = rem >> 1;
    int seg = rem & 1;
    int base = seg * OWN;
    int wp  = threadIdx.x;                // 0..159; active if < WIN
    bool act = wp < WIN;

    int j = (base + wp - HALO) & 255;     // circular column
    int p = (row << 8) | j;

    uint32_t ciy = (uint32_t)(b * 131072 + p);
    uint32_t cix = ciy + 65536u;

    float y = 0.0f, x = 0.0f, d = 0.0f;
    float4 ny4 = make_float4(0.f, 0.f, 0.f, 0.f), nx4 = ny4;
    if (act) {
        y = __fmul_rn(bits_to_f01(rnd32(ka, kb, ciy)), 255.0f);
        x = __fmul_rn(bits_to_f01(rnd32(ka, kb, cix)), 255.0f);
        d = __ldg(&g_D[daddr(b, y, x)]);
        ny4 = __ldg(&g_N4[ciy]);          // iteration 0 normals
        nx4 = __ldg(&g_N4[cix]);
    }

    int tm = max(wp - 1, 0);              // clamped: edges are eroded anyway
    int tp = min(wp + 1, WIN - 1);

#pragma unroll
    for (int it = 0; it < 5; it++) {
        int cb = it & 1;
        if (act) { sy[cb][wp] = y; sx[cb][wp] = x; sd[cb][wp] = d; }

        // prefetch next iteration's normals (hidden under sync + gather walls)
        float4 ny4n = make_float4(0.f, 0.f, 0.f, 0.f), nx4n = ny4n;
        if (act && it < 4) {
            uint32_t nb = (uint32_t)(it + 1) * 262144u;
            ny4n = __ldg(&g_N4[nb + ciy]);
            nx4n = __ldg(&g_N4[nb + cix]);
        }

        __syncthreads();
        float my = sy[cb][tm], mx = sx[cb][tm], md = sd[cb][tm];
        float qy = sy[cb][tp], qx = sx[cb][tp], qd = sd[cb][tp];
        // single sync per iteration: next iteration writes the other buffer

        if (act) {
            // propagate(+1) at j and j+1, then propagate(-1) at j
            float c0y, c0x, c0d, c1y, c1x, c1d;
            if (md < d) { c0y = my; c0x = mx; c0d = md; } else { c0y = y; c0x = x; c0d = d; }
            if (d < qd) { c1y = y;  c1x = x;  c1d = d;  } else { c1y = qy; c1x = qx; c1d = qd; }
            if (c1d < c0d) { y = c1y; x = c1x; d = c1d; } else { y = c0y; x = c0x; d = c0d; }

            // ---- speculative pair (steps 0,1): scales 1.0, 0.5 ----
            {
                float a1y = clipc(__fadd_rn(y, __fmul_rn(ny4.x, 1.0f)));
                float a1x = clipc(__fadd_rn(x, __fmul_rn(nx4.x, 1.0f)));
                float r0y = clipc(__fadd_rn(y,   __fmul_rn(ny4.y, 0.5f)));
                float r0x = clipc(__fadd_rn(x,   __fmul_rn(nx4.y, 0.5f)));
                float r1y = clipc(__fadd_rn(a1y, __fmul_rn(ny4.y, 0.5f)));
                float r1x = clipc(__fadd_rn(a1x, __fmul_rn(nx4.y, 0.5f)));
                float d1  = __ldg(&g_D[daddr(b, a1y, a1x)]);
                float d20 = __ldg(&g_D[daddr(b, r0y, r0x)]);
                float d21 = __ldg(&g_D[daddr(b, r1y, r1x)]);
                bool acc1 = d1 < d;
                if (acc1) { y = a1y; x = a1x; d = d1; }
                float dv = acc1 ? d21 : d20;
                float cy = acc1 ? r1y : r0y;
                float cx = acc1 ? r1x : r0x;
                if (dv < d) { y = cy; x = cx; d = dv; }
            }
            // ---- speculative pair (steps 2,3): scales 0.25, 0.125 ----
            {
                float a1y = clipc(__fadd_rn(y, __fmul_rn(ny4.z, 0.25f)));
                float a1x = clipc(__fadd_rn(x, __fmul_rn(nx4.z, 0.25f)));
                float r0y = clipc(__fadd_rn(y,   __fmul_rn(ny4.w, 0.125f)));
                float r0x = clipc(__fadd_rn(x,   __fmul_rn(nx4.w, 0.125f)));
                float r1y = clipc(__fadd_rn(a1y, __fmul_rn(ny4.w, 0.125f)));
                float r1x = clipc(__fadd_rn(a1x, __fmul_rn(nx4.w, 0.125f)));
                float d1  = __ldg(&g_D[daddr(b, a1y, a1x)]);
                float d20 = __ldg(&g_D[daddr(b, r0y, r0x)]);
                float d21 = __ldg(&g_D[daddr(b, r1y, r1x)]);
                bool acc1 = d1 < d;
                if (acc1) { y = a1y; x = a1x; d = d1; }
                float dv = acc1 ? d21 : d20;
                float cy = acc1 ? r1y : r0y;
                float cx = acc1 ? r1x : r0x;
                if (dv < d) { y = cy; x = cx; d = dv; }
            }
        }
        ny4 = ny4n; nx4 = nx4n;
    }

    if (wp >= HALO && wp < HALO + OWN) {
        out[b * 131072 + p]        = y;
        out[b * 131072 + NPIX + p] = x;
    }
}

// ---------------- host ----------------
extern "C" void kernel_launch(void* const* d_in, const int* in_sizes, int n_in,
                              void* d_out, int out_size) {
    const float* src = (const float*)d_in[0];
    const float* tgt = (const float*)d_in[1];
    float* out = (float*)d_out;
    (void)in_sizes; (void)n_in; (void)out_size;

    uint32_t ki0, ki1, kl0, kl1;
    threefry(0u, 1u, 0u, 0u, ki0, ki1);   // k_init
    threefry(0u, 1u, 0u, 1u, kl0, kl1);   // k_loop

    AllKeys keys;
    for (uint32_t t = 0; t < 5; t++) {
        uint32_t K0, K1;
        threefry(kl0, kl1, 0u, t, K0, K1);        // fold_in(k_loop, t)
        for (int s = 0; s < 4; s++) {
            uint32_t n0, n1, s0, s1;
            threefry(K0, K1, 0u, 0u, n0, n1);     // next key
            threefry(K0, K1, 0u, 1u, s0, s1);     // key for normal draw
            keys.k[t][s][0] = s0;
            keys.k[t][s][1] = s1;
            K0 = n0; K1 = n1;
        }
    }

    kPrep<<<1536, 256>>>(src, tgt, keys);
    kMatch<<<1024, MTHREADS>>>(out, ki0, ki1);
}